// round 1
// baseline (speedup 1.0000x reference)
#include <cuda_runtime.h>
#include <cfloat>

#define BB 256
#define TT 512
#define KK 128
#define TRP 132   // padded transposed-transitions row (conflict-free LDS.128)

// Scratch (allowed: __device__ globals, no runtime allocation)
__device__ float g_states[(size_t)BB * TT * KK];   // 64 MiB: S_t per (b,t)
__device__ int   g_tags[BB * TT];                  // decoded tags

// ---------------------------------------------------------------------------
// Forward Viterbi: per-batch CTA, 128 threads (thread j owns output tag j).
// new[j] = pot[t][j] + max_i(S[i] + trans[i][j]); stop at t = len-1 (mask).
// Stores S_0..S_{len-1} to g_states.
// ---------------------------------------------------------------------------
__global__ void __launch_bounds__(128) fwd_kernel(
    const float* __restrict__ pot,
    const float* __restrict__ trans,
    const int*   __restrict__ lens)
{
    extern __shared__ float sm[];
    float* tr = sm;                 // KK * TRP floats (transposed transitions)
    float* st = sm + KK * TRP;      // 2 * KK floats (ping-pong state)

    const int b = blockIdx.x;
    const int j = threadIdx.x;

    // Load transitions transposed: tr[j*TRP + i] = trans[i*KK + j]
    // (coalesced global reads; minor one-time STS conflicts)
    #pragma unroll 4
    for (int i = 0; i < KK; ++i)
        tr[j * TRP + i] = trans[i * KK + j];

    const int len = lens[b];
    const int base = b * TT * KK;

    float s0 = pot[base + j];
    st[j] = s0;
    g_states[base + j] = s0;
    __syncthreads();

    const float* trj = &tr[j * TRP];
    int p = 0;
    for (int t = 1; t < len; ++t) {
        // prefetch this step's emission early
        float x = pot[base + t * KK + j];

        const float* sp = st + p * KK;
        float b0 = -FLT_MAX, b1 = -FLT_MAX, b2 = -FLT_MAX, b3 = -FLT_MAX;
        #pragma unroll
        for (int i = 0; i < KK; i += 4) {
            float4 s4 = *reinterpret_cast<const float4*>(sp + i);   // broadcast
            float4 t4 = *reinterpret_cast<const float4*>(trj + i);  // conflict-free
            b0 = fmaxf(b0, s4.x + t4.x);
            b1 = fmaxf(b1, s4.y + t4.y);
            b2 = fmaxf(b2, s4.z + t4.z);
            b3 = fmaxf(b3, s4.w + t4.w);
        }
        float ns = x + fmaxf(fmaxf(b0, b1), fmaxf(b2, b3));

        st[(p ^ 1) * KK + j] = ns;
        g_states[base + t * KK + j] = ns;
        __syncthreads();
        p ^= 1;
    }
}

// ---------------------------------------------------------------------------
// Backtrace: per-batch CTA, 128 threads load transposed transitions to smem,
// then warp 0 chases tags backward, recomputing the needed argmax per step.
// Tie-break: first (smallest) index wins, matching jnp.argmax.
// ---------------------------------------------------------------------------
__global__ void __launch_bounds__(128) bwd_kernel(
    const float* __restrict__ trans,
    const int*   __restrict__ lens)
{
    extern __shared__ float tr[];   // KK * TRP floats
    const int b   = blockIdx.x;
    const int tid = threadIdx.x;

    #pragma unroll 4
    for (int i = 0; i < KK; ++i)
        tr[tid * TRP + i] = trans[i * KK + tid];

    const int len = lens[b];

    // tags beyond the sequence are 0 (masked backpointers in the reference)
    for (int t = len + tid; t < TT; t += blockDim.x)
        g_tags[b * TT + t] = 0;

    __syncthreads();
    if (tid >= 32) return;          // warp 0 only from here

    const int l = tid;
    const unsigned FULL = 0xffffffffu;
    const int base = b * TT * KK;

    // ---- initial tag: argmax_j S_{len-1}[j] ----
    {
        const float* S = &g_states[base + (len - 1) * KK];
        float4 v4 = *reinterpret_cast<const float4*>(S + 4 * l);
        float bv = v4.x; int bi = 4 * l;
        if (v4.y > bv) { bv = v4.y; bi = 4 * l + 1; }
        if (v4.z > bv) { bv = v4.z; bi = 4 * l + 2; }
        if (v4.w > bv) { bv = v4.w; bi = 4 * l + 3; }
        #pragma unroll
        for (int d = 16; d > 0; d >>= 1) {
            float ov = __shfl_down_sync(FULL, bv, d);
            int   oi = __shfl_down_sync(FULL, bi, d);
            if (ov > bv || (ov == bv && oi < bi)) { bv = ov; bi = oi; }
        }
        int tag = __shfl_sync(FULL, bi, 0);
        if (l == 0) g_tags[b * TT + (len - 1)] = tag;

        // ---- walk backward: tag_t = argmax_i (S_t[i] + trans[i][tag_{t+1}]) ----
        for (int t = len - 2; t >= 0; --t) {
            const float* St = &g_states[base + t * KK];
            float4 s4 = *reinterpret_cast<const float4*>(St + 4 * l);
            float4 t4 = *reinterpret_cast<const float4*>(&tr[tag * TRP + 4 * l]);
            float v0 = s4.x + t4.x;
            float v1 = s4.y + t4.y;
            float v2 = s4.z + t4.z;
            float v3 = s4.w + t4.w;
            bv = v0; bi = 4 * l;
            if (v1 > bv) { bv = v1; bi = 4 * l + 1; }
            if (v2 > bv) { bv = v2; bi = 4 * l + 2; }
            if (v3 > bv) { bv = v3; bi = 4 * l + 3; }
            #pragma unroll
            for (int d = 16; d > 0; d >>= 1) {
                float ov = __shfl_down_sync(FULL, bv, d);
                int   oi = __shfl_down_sync(FULL, bi, d);
                if (ov > bv || (ov == bv && oi < bi)) { bv = ov; bi = oi; }
            }
            tag = __shfl_sync(FULL, bi, 0);
            if (l == 0) g_tags[b * TT + t] = tag;
        }
    }
}

// ---------------------------------------------------------------------------
// One-hot fill: out[b,t,k] = (k == tag[b,t]). Pure HBM write, float4 stores.
// ---------------------------------------------------------------------------
__global__ void __launch_bounds__(256) fill_kernel(float* __restrict__ out)
{
    int gid = blockIdx.x * blockDim.x + threadIdx.x;   // BB*TT*32 threads
    int row = gid >> 5;                                // b*TT + t
    int q   = (gid & 31) * 4;
    int tag = g_tags[row];
    float4 r;
    r.x = (q     == tag) ? 1.0f : 0.0f;
    r.y = (q + 1 == tag) ? 1.0f : 0.0f;
    r.z = (q + 2 == tag) ? 1.0f : 0.0f;
    r.w = (q + 3 == tag) ? 1.0f : 0.0f;
    reinterpret_cast<float4*>(out)[gid] = r;
}

// ---------------------------------------------------------------------------
extern "C" void kernel_launch(void* const* d_in, const int* in_sizes, int n_in,
                              void* d_out, int out_size)
{
    const float* pot   = (const float*)d_in[0];   // (B,T,K) f32
    const float* trans = (const float*)d_in[1];   // (K,K)   f32
    const int*   lens  = (const int*)  d_in[2];   // (B,)    i32
    float* out = (float*)d_out;                   // (B,T,K) f32

    const int fwd_smem = (KK * TRP + 2 * KK) * (int)sizeof(float);  // 68,608 B
    const int bwd_smem = (KK * TRP) * (int)sizeof(float);           // 67,584 B

    cudaFuncSetAttribute(fwd_kernel, cudaFuncAttributeMaxDynamicSharedMemorySize, fwd_smem);
    cudaFuncSetAttribute(bwd_kernel, cudaFuncAttributeMaxDynamicSharedMemorySize, bwd_smem);

    fwd_kernel<<<BB, 128, fwd_smem>>>(pot, trans, lens);
    bwd_kernel<<<BB, 128, bwd_smem>>>(trans, lens);

    int total_vec4 = BB * TT * (KK / 4);          // 4,194,304 threads
    fill_kernel<<<total_vec4 / 256, 256>>>(out);
}

// round 2
// speedup vs baseline: 1.8326x; 1.8326x over previous
#include <cuda_runtime.h>
#include <cfloat>

#define BB 256
#define TT 512
#define KK 128
#define TRP 132   // padded transposed-transitions row stride (floats)

// Scratch (__device__ globals only — no runtime allocation)
__device__ float g_states[(size_t)BB * TT * KK];   // 64 MiB Viterbi states
__device__ int   g_order[BB];                      // bid -> batch mapping

// ---------------------------------------------------------------------------
// Rank-sort batches by descending length; pair long with short so each SM
// (which gets bid i and bid i+148 under the classic placement LUT) carries a
// balanced number of total steps.
// ---------------------------------------------------------------------------
__global__ void order_kernel(const int* __restrict__ lens)
{
    __shared__ int sl[BB];
    const int b = threadIdx.x;
    sl[b] = lens[b];
    __syncthreads();
    const int L = sl[b];
    int r = 0;
    #pragma unroll 8
    for (int i = 0; i < BB; ++i) {
        int Li = sl[i];
        r += (Li > L) || (Li == L && i < b);
    }
    // rank r in [0,148) -> bid r (wave-1 slot); rank r in [148,256) -> bid 403-r
    g_order[(r < 148) ? r : (403 - r)] = b;
}

// ---------------------------------------------------------------------------
// Helpers for the backtrace argmax (warp-uniform, first-index tie-break)
// ---------------------------------------------------------------------------
__device__ __forceinline__ unsigned redux_max_u32(unsigned v) {
    unsigned r;
    asm("redux.sync.max.u32 %0, %1, 0xffffffff;" : "=r"(r) : "r"(v));
    return r;
}
__device__ __forceinline__ unsigned redux_min_u32(unsigned v) {
    unsigned r;
    asm("redux.sync.min.u32 %0, %1, 0xffffffff;" : "=r"(r) : "r"(v));
    return r;
}
// Order-preserving float -> uint key
__device__ __forceinline__ unsigned fkey(float f) {
    unsigned u = __float_as_uint(f);
    return u ^ ((unsigned)((int)u >> 31) | 0x80000000u);
}

// Warp-collective argmax over 128 values (lane l holds elements 4l..4l+3).
// Ties -> smallest index (matches jnp.argmax). Result uniform across lanes.
__device__ __forceinline__ int argmax128(float4 v, int l)
{
    unsigned k0 = fkey(v.x), k1 = fkey(v.y), k2 = fkey(v.z), k3 = fkey(v.w);
    unsigned km = max(max(k0, k1), max(k2, k3));
    unsigned M  = redux_max_u32(km);
    unsigned il = 0xFFFFFFFFu;
    if (k3 == M) il = 4 * l + 3;
    if (k2 == M) il = 4 * l + 2;
    if (k1 == M) il = 4 * l + 1;
    if (k0 == M) il = 4 * l + 0;
    return (int)redux_min_u32(il);
}

// One backtrace step: given S_t (cur) and tag_{t+1}, compute tag_t and write
// the one-hot output row t. addtr=false for the init step (plain argmax of S).
__device__ __forceinline__ void bt_step(float4 cur, const float* __restrict__ s_tr,
                                        int& tag, float* __restrict__ outrow,
                                        int l, bool addtr)
{
    if (addtr) {
        float4 tc = *reinterpret_cast<const float4*>(&s_tr[tag * TRP + 4 * l]);
        cur.x += tc.x; cur.y += tc.y; cur.z += tc.z; cur.w += tc.w;
    }
    tag = argmax128(cur, l);
    float4 r;
    r.x = (4 * l + 0 == tag) ? 1.0f : 0.0f;
    r.y = (4 * l + 1 == tag) ? 1.0f : 0.0f;
    r.z = (4 * l + 2 == tag) ? 1.0f : 0.0f;
    r.w = (4 * l + 3 == tag) ? 1.0f : 0.0f;
    reinterpret_cast<float4*>(outrow)[l] = r;
}

// ---------------------------------------------------------------------------
// Fused Viterbi forward + backtrace + one-hot write. One CTA per batch,
// 128 threads. Transitions column j lives in thread j's registers.
// ---------------------------------------------------------------------------
__global__ void __launch_bounds__(128, 2) crf_kernel(
    const float* __restrict__ pot,
    const float* __restrict__ trans,
    const int*   __restrict__ lens,
    float*       __restrict__ out)
{
    extern __shared__ float sm[];
    float* s_tr = sm;                 // KK*TRP floats: transposed transitions
    float* s_st = sm + KK * TRP;      // 2*KK floats: ping-pong state

    const int j = threadIdx.x;
    const int b = g_order[blockIdx.x];
    const int len = lens[b];
    const size_t base = (size_t)b * TT * KK;

    // Load transitions column j into registers AND stage transposed copy in
    // smem (row j of s_tr) for the backtrace.
    float4 a[32];
    #pragma unroll
    for (int q = 0; q < 32; ++q) {
        float4 v;
        v.x = trans[(4 * q + 0) * KK + j];
        v.y = trans[(4 * q + 1) * KK + j];
        v.z = trans[(4 * q + 2) * KK + j];
        v.w = trans[(4 * q + 3) * KK + j];
        a[q] = v;
        *reinterpret_cast<float4*>(&s_tr[j * TRP + 4 * q]) = v;
    }

    float s0 = pot[base + j];
    s_st[j] = s0;
    g_states[base + j] = s0;
    __syncthreads();

    // ---- forward Viterbi ----
    int p = 0;
    for (int t = 1; t < len; ++t) {
        float x = pot[base + (size_t)t * KK + j];
        const float4* sp = reinterpret_cast<const float4*>(&s_st[p * KK]);
        float m0 = -FLT_MAX, m1 = -FLT_MAX, m2 = -FLT_MAX, m3 = -FLT_MAX;
        #pragma unroll
        for (int q = 0; q < 32; ++q) {
            float4 s4 = sp[q];                       // broadcast LDS.128
            m0 = fmaxf(m0, s4.x + a[q].x);
            m1 = fmaxf(m1, s4.y + a[q].y);
            m2 = fmaxf(m2, s4.z + a[q].z);
            m3 = fmaxf(m3, s4.w + a[q].w);
        }
        float ns = x + fmaxf(fmaxf(m0, m1), fmaxf(m2, m3));
        s_st[(p ^ 1) * KK + j] = ns;
        g_states[base + (size_t)t * KK + j] = ns;
        __syncthreads();
        p ^= 1;
    }

    // ---- epilogue: warp 0 backtraces; warps 1-3 write tag-0 rows >= len ----
    if (j >= 32) {
        const int total = (TT - len) * 32;
        for (int idx = j - 32; idx < total; idx += 96) {
            int r = len + (idx >> 5);
            int c = idx & 31;
            float4 v = make_float4(c == 0 ? 1.0f : 0.0f, 0.0f, 0.0f, 0.0f);
            reinterpret_cast<float4*>(out + base + (size_t)r * KK)[c] = v;
        }
        return;
    }

    const int l = j;
    auto LDst = [&](int t) -> float4 {
        if (t < 0) return make_float4(0.f, 0.f, 0.f, 0.f);
        return reinterpret_cast<const float4*>(&g_states[base + (size_t)t * KK])[l];
    };
    float* const ob = out + base;

    int tag = 0;
    float4 c0 = LDst(len - 1);
    int t = len - 2;
    // depth-4 prefetch ring (loads are tag-independent)
    float4 p0 = LDst(t), p1 = LDst(t - 1), p2 = LDst(t - 2), p3 = LDst(t - 3);

    bt_step(c0, s_tr, tag, ob + (size_t)(len - 1) * KK, l, false);

    while (t >= 3) {
        bt_step(p0, s_tr, tag, ob + (size_t)(t    ) * KK, l, true);  p0 = LDst(t - 4);
        bt_step(p1, s_tr, tag, ob + (size_t)(t - 1) * KK, l, true);  p1 = LDst(t - 5);
        bt_step(p2, s_tr, tag, ob + (size_t)(t - 2) * KK, l, true);  p2 = LDst(t - 6);
        bt_step(p3, s_tr, tag, ob + (size_t)(t - 3) * KK, l, true);  p3 = LDst(t - 7);
        t -= 4;
    }
    if (t >= 0) bt_step(p0, s_tr, tag, ob + (size_t)(t    ) * KK, l, true);
    if (t >= 1) bt_step(p1, s_tr, tag, ob + (size_t)(t - 1) * KK, l, true);
    if (t >= 2) bt_step(p2, s_tr, tag, ob + (size_t)(t - 2) * KK, l, true);
}

// ---------------------------------------------------------------------------
extern "C" void kernel_launch(void* const* d_in, const int* in_sizes, int n_in,
                              void* d_out, int out_size)
{
    const float* pot   = (const float*)d_in[0];   // (B,T,K) f32
    const float* trans = (const float*)d_in[1];   // (K,K)   f32
    const int*   lens  = (const int*)  d_in[2];   // (B,)    i32
    float* out = (float*)d_out;                   // (B,T,K) f32

    const int smem = (KK * TRP + 2 * KK) * (int)sizeof(float);   // 68,608 B
    cudaFuncSetAttribute(crf_kernel, cudaFuncAttributeMaxDynamicSharedMemorySize, smem);

    order_kernel<<<1, BB>>>(lens);
    crf_kernel<<<BB, 128, smem>>>(pot, trans, lens, out);
}